// round 2
// baseline (speedup 1.0000x reference)
#include <cuda_runtime.h>
#include <cuda_bf16.h>
#include <cstdint>
#include <cstddef>

#define N_ROWS 131072
#define DIM    512
#define NCLU   512

// ---------------------------------------------------------------------------
// Device-global scratch
// ---------------------------------------------------------------------------
__device__ __nv_bfloat16 g_xb[(size_t)N_ROWS * DIM];
__device__ float g_x2[N_ROWS];
__device__ __nv_bfloat16 g_cb[(size_t)NCLU * DIM];
__device__ float g_c2[NCLU];

// ---------------------------------------------------------------------------
// Helpers (base ISA only: sm_80/sm_90 features, no 'a' suffix anything)
// ---------------------------------------------------------------------------
__device__ __forceinline__ uint32_t smem_to_u32(const void* smem_ptr) {
    uint32_t addr;
    asm("{ .reg .u64 tmp; cvta.to.shared.u64 tmp, %1; cvt.u32.u64 %0, tmp; }"
        : "=r"(addr) : "l"(smem_ptr));
    return addr;
}
__device__ __forceinline__ void cp16(uint32_t dst_smem, const void* src) {
    asm volatile("cp.async.cg.shared.global [%0], [%1], 16;"
                 :: "r"(dst_smem), "l"(src));
}
__device__ __forceinline__ void cp_commit() {
    asm volatile("cp.async.commit_group;");
}
template <int N>
__device__ __forceinline__ void cp_wait() {
    asm volatile("cp.async.wait_group %0;" :: "n"(N));
}
__device__ __forceinline__ float frcp(float a) {
    float r;
    asm("rcp.approx.f32 %0, %1;" : "=f"(r) : "f"(a));
    return r;
}
__device__ __forceinline__ void ldsm4(uint32_t* r, uint32_t addr) {
    asm volatile("ldmatrix.sync.aligned.m8n8.x4.shared.b16 {%0,%1,%2,%3}, [%4];"
                 : "=r"(r[0]), "=r"(r[1]), "=r"(r[2]), "=r"(r[3]) : "r"(addr));
}
__device__ __forceinline__ void mma16816(float* c, const uint32_t* a, const uint32_t* b) {
    asm volatile(
        "mma.sync.aligned.m16n8k16.row.col.f32.bf16.bf16.f32 "
        "{%0,%1,%2,%3}, {%4,%5,%6,%7}, {%8,%9}, {%0,%1,%2,%3};"
        : "+f"(c[0]), "+f"(c[1]), "+f"(c[2]), "+f"(c[3])
        : "r"(a[0]), "r"(a[1]), "r"(a[2]), "r"(a[3]), "r"(b[0]), "r"(b[1]));
}

// ---------------------------------------------------------------------------
// Prep: fp32 -> bf16 + row squared norms (one row per warp)
// ---------------------------------------------------------------------------
__device__ __forceinline__ void prep_row(const float* __restrict__ src,
                                         __nv_bfloat16* __restrict__ dstb,
                                         float* __restrict__ dst2, int row) {
    int lane = threadIdx.x & 31;
    const float4* sr = (const float4*)(src + (size_t)row * DIM);
    uint2* dr = (uint2*)(dstb + (size_t)row * DIM);
    float s = 0.f;
    #pragma unroll
    for (int t = 0; t < 4; t++) {
        float4 v = sr[lane + 32 * t];
        s += v.x * v.x + v.y * v.y + v.z * v.z + v.w * v.w;
        union { __nv_bfloat162 h[2]; uint2 u; } pk;
        pk.h[0] = __floats2bfloat162_rn(v.x, v.y);
        pk.h[1] = __floats2bfloat162_rn(v.z, v.w);
        dr[lane + 32 * t] = pk.u;
    }
    #pragma unroll
    for (int o = 16; o; o >>= 1) s += __shfl_xor_sync(0xffffffffu, s, o);
    if (lane == 0) dst2[row] = s;
}
__global__ void prep_x_kernel(const float* __restrict__ x) {
    int row = blockIdx.x * 8 + (threadIdx.x >> 5);
    if (row < N_ROWS) prep_row(x, g_xb, g_x2, row);
}
__global__ void prep_c_kernel(const float* __restrict__ c) {
    int row = blockIdx.x * 8 + (threadIdx.x >> 5);
    if (row < NCLU) prep_row(c, g_cb, g_c2, row);
}

// ---------------------------------------------------------------------------
// GEMM + fused t-student epilogue.
// CTA tile 128x256 (cluster of 2 CTAs covers the full 512 clusters of the same
// 128 rows; row sums exchanged via DSMEM). 256 threads, 8 warps (4 m x 2 n),
// warp tile 32x128. cp.async 3-stage pipeline, KC=64, SW128 swizzle.
// ---------------------------------------------------------------------------
static constexpr int TM = 128, TN = 256, KC = 64, NUM_KC = DIM / KC;  // 8
static constexpr int A_BYTES = TM * KC * 2;   // 16384
static constexpr int B_BYTES = TN * KC * 2;   // 32768
static constexpr int A_OFF   = 0;
static constexpr int B_OFF   = 3 * A_BYTES;            // 49152
static constexpr int C2_OFF  = B_OFF + 3 * B_BYTES;    // 147456
static constexpr int X2_OFF  = C2_OFF + NCLU * 4;      // 149504
static constexpr int RED_OFF = X2_OFF + TM * 4;        // 150016  (128 rows x 2 warp_n)
static constexpr int PEER_OFF = RED_OFF + TM * 2 * 4;  // 151040
static constexpr int INV_OFF  = PEER_OFF + TM * 4;     // 151552
static constexpr int SMEM_TOTAL = INV_OFF + TM * 4;    // 152064

__global__ void __launch_bounds__(256, 1) __cluster_dims__(2, 1, 1)
gemm_kernel(float* __restrict__ out) {
    extern __shared__ __align__(1024) char smem[];
    uint32_t sb = smem_to_u32(smem);
    int tid = threadIdx.x;
    int wid = tid >> 5, lane = tid & 31;
    int mtile = blockIdx.x >> 1;
    int nhalf = blockIdx.x & 1;
    int warp_m = wid & 3;        // 4 x 32 rows
    int warp_n = wid >> 2;       // 2 x 128 cols

    float* c2s  = (float*)(smem + C2_OFF);
    float* x2s  = (float*)(smem + X2_OFF);
    float* red  = (float*)(smem + RED_OFF);
    float* peer = (float*)(smem + PEER_OFF);
    float* invs = (float*)(smem + INV_OFF);

    for (int i = tid; i < NCLU; i += 256) c2s[i] = g_c2[i];
    for (int i = tid; i < TM; i += 256)   x2s[i] = g_x2[(size_t)mtile * TM + i];

    const __nv_bfloat16* asrc0 = g_xb + (size_t)mtile * TM * DIM;
    const __nv_bfloat16* bsrc0 = g_cb + (size_t)nhalf * TN * DIM;

    auto load_chunk = [&](int kc, int s) {
        uint32_t Ab = sb + A_OFF + s * A_BYTES;
        uint32_t Bb = sb + B_OFF + s * B_BYTES;
        const __nv_bfloat16* asrc = asrc0 + kc * KC;
        const __nv_bfloat16* bsrc = bsrc0 + kc * KC;
        #pragma unroll
        for (int i = 0; i < 4; i++) {       // A: 1024 16B chunks
            int idx = tid + i * 256;
            int r = idx >> 3, c = idx & 7;
            cp16(Ab + r * 128 + ((c * 16) ^ ((r & 7) << 4)),
                 asrc + (size_t)r * DIM + c * 8);
        }
        #pragma unroll
        for (int i = 0; i < 8; i++) {       // B: 2048 16B chunks
            int idx = tid + i * 256;
            int r = idx >> 3, c = idx & 7;
            cp16(Bb + r * 128 + ((c * 16) ^ ((r & 7) << 4)),
                 bsrc + (size_t)r * DIM + c * 8);
        }
        cp_commit();
    };

    // ldmatrix per-lane addressing (group = lane>>3, row-in-group = lane&7)
    int ri = lane & 7;
    uint32_t mask  = (uint32_t)ri << 4;                 // swizzle XOR (row&7)<<4 == ri<<4
    uint32_t a_row0 = (uint32_t)(warp_m * 32 + ((lane >> 3) & 1) * 8 + ri) * 128;
    uint32_t akoff  = (uint32_t)(lane >> 4) * 16;
    uint32_t b_row0 = (uint32_t)(warp_n * 128 + (lane >> 4) * 8 + ri) * 128;
    uint32_t bkoff  = (uint32_t)((lane >> 3) & 1) * 16;

    float acc[2][16][4] = {};   // warp tile 32x128: 2 m16 x 16 n8

    // Prologue: stages 0,1
    load_chunk(0, 0);
    load_chunk(1, 1);

    for (int kc = 0; kc < NUM_KC; kc++) {
        int s = kc % 3;
        if (kc < NUM_KC - 1) cp_wait<1>(); else cp_wait<0>();
        __syncthreads();
        if (kc + 2 < NUM_KC) load_chunk(kc + 2, (kc + 2) % 3);

        uint32_t Ab = sb + A_OFF + s * A_BYTES;
        uint32_t Bb = sb + B_OFF + s * B_BYTES;
        #pragma unroll
        for (int ks = 0; ks < 4; ks++) {
            uint32_t a[2][4], b[32];
            uint32_t akb = (akoff + ks * 32) ^ mask;
            uint32_t bkb = (bkoff + ks * 32) ^ mask;
            ldsm4(a[0], Ab + a_row0 + akb);
            ldsm4(a[1], Ab + a_row0 + 2048 + akb);
            #pragma unroll
            for (int gg = 0; gg < 8; gg++)
                ldsm4(b + gg * 4, Bb + b_row0 + gg * 2048 + bkb);
            #pragma unroll
            for (int mt = 0; mt < 2; mt++)
                #pragma unroll
                for (int nt = 0; nt < 16; nt++)
                    mma16816(acc[mt][nt], a[mt], b + nt * 2);
        }
    }

    // ---------------- Epilogue ----------------
    int g = lane >> 2, qa = lane & 3;
    float rs[2][2];
    #pragma unroll
    for (int mt = 0; mt < 2; mt++) {
        #pragma unroll
        for (int h = 0; h < 2; h++) {
            int row = warp_m * 32 + mt * 16 + h * 8 + g;
            float x2v = x2s[row];
            float p = 0.f;
            #pragma unroll
            for (int nt = 0; nt < 16; nt++) {
                int col = nhalf * 256 + warp_n * 128 + nt * 8 + qa * 2;
                float b0 = x2v + c2s[col];
                float b1 = x2v + c2s[col + 1];
                float q0 = frcp(1.f + fmaxf(fmaf(-2.f, acc[mt][nt][h * 2 + 0], b0), 0.f));
                float q1 = frcp(1.f + fmaxf(fmaf(-2.f, acc[mt][nt][h * 2 + 1], b1), 0.f));
                acc[mt][nt][h * 2 + 0] = q0;
                acc[mt][nt][h * 2 + 1] = q1;
                p += q0 + q1;
            }
            rs[mt][h] = p;
        }
    }
    #pragma unroll
    for (int mt = 0; mt < 2; mt++)
        #pragma unroll
        for (int h = 0; h < 2; h++) {
            rs[mt][h] += __shfl_xor_sync(0xffffffffu, rs[mt][h], 1);
            rs[mt][h] += __shfl_xor_sync(0xffffffffu, rs[mt][h], 2);
        }
    if (qa == 0) {
        #pragma unroll
        for (int mt = 0; mt < 2; mt++)
            #pragma unroll
            for (int h = 0; h < 2; h++)
                red[(warp_m * 32 + mt * 16 + h * 8 + g) * 2 + warp_n] = rs[mt][h];
    }
    __syncthreads();

    float L = 0.f;
    if (tid < TM) {
        L = red[tid * 2] + red[tid * 2 + 1];
        uint32_t paddr;
        asm volatile("mapa.shared::cluster.u32 %0, %1, %2;"
                     : "=r"(paddr) : "r"(sb + PEER_OFF + tid * 4), "r"(nhalf ^ 1));
        asm volatile("st.shared::cluster.f32 [%0], %1;" :: "r"(paddr), "f"(L) : "memory");
    }
    asm volatile("barrier.cluster.arrive.aligned;" ::: "memory");
    asm volatile("barrier.cluster.wait.aligned;" ::: "memory");
    if (tid < TM) invs[tid] = frcp(L + peer[tid]);
    __syncthreads();

    float* outbase = out + (size_t)mtile * TM * NCLU + nhalf * TN;
    #pragma unroll
    for (int mt = 0; mt < 2; mt++) {
        #pragma unroll
        for (int h = 0; h < 2; h++) {
            int row = warp_m * 32 + mt * 16 + h * 8 + g;
            float inv = invs[row];
            float* orow = outbase + (size_t)row * NCLU + warp_n * 128;
            #pragma unroll
            for (int nt = 0; nt < 16; nt++) {
                float2 v;
                v.x = acc[mt][nt][h * 2 + 0] * inv;
                v.y = acc[mt][nt][h * 2 + 1] * inv;
                *(float2*)(orow + nt * 8 + qa * 2) = v;
            }
        }
    }
}

// ---------------------------------------------------------------------------
// Launch
// ---------------------------------------------------------------------------
extern "C" void kernel_launch(void* const* d_in, const int* in_sizes, int n_in,
                              void* d_out, int out_size) {
    const float* x  = (const float*)d_in[0];
    const float* cc = (const float*)d_in[1];
    float* out = (float*)d_out;

    cudaFuncSetAttribute(gemm_kernel,
                         cudaFuncAttributeMaxDynamicSharedMemorySize, SMEM_TOTAL);

    prep_x_kernel<<<N_ROWS / 8, 256>>>(x);
    prep_c_kernel<<<NCLU / 8, 256>>>(cc);
    gemm_kernel<<<(N_ROWS / TM) * 2, 256, SMEM_TOTAL>>>(out);
}

// round 3
// speedup vs baseline: 1.0261x; 1.0261x over previous
#include <cuda_runtime.h>
#include <cuda_bf16.h>
#include <cstdint>
#include <cstddef>

#define N_ROWS 131072
#define DIM    512
#define NCLU   512

// ---------------------------------------------------------------------------
// Device-global scratch (centers only now)
// ---------------------------------------------------------------------------
__device__ __nv_bfloat16 g_cb[(size_t)NCLU * DIM];
__device__ float g_c2[NCLU];

// ---------------------------------------------------------------------------
// Helpers (base ISA only)
// ---------------------------------------------------------------------------
__device__ __forceinline__ uint32_t smem_to_u32(const void* smem_ptr) {
    uint32_t addr;
    asm("{ .reg .u64 tmp; cvta.to.shared.u64 tmp, %1; cvt.u32.u64 %0, tmp; }"
        : "=r"(addr) : "l"(smem_ptr));
    return addr;
}
__device__ __forceinline__ void cp16(uint32_t dst_smem, const void* src) {
    asm volatile("cp.async.cg.shared.global [%0], [%1], 16;"
                 :: "r"(dst_smem), "l"(src));
}
__device__ __forceinline__ void cp_commit() {
    asm volatile("cp.async.commit_group;");
}
template <int N>
__device__ __forceinline__ void cp_wait() {
    asm volatile("cp.async.wait_group %0;" :: "n"(N));
}
__device__ __forceinline__ float frcp(float a) {
    float r;
    asm("rcp.approx.f32 %0, %1;" : "=f"(r) : "f"(a));
    return r;
}
__device__ __forceinline__ void ldsm4(uint32_t* r, uint32_t addr) {
    asm volatile("ldmatrix.sync.aligned.m8n8.x4.shared.b16 {%0,%1,%2,%3}, [%4];"
                 : "=r"(r[0]), "=r"(r[1]), "=r"(r[2]), "=r"(r[3]) : "r"(addr));
}
__device__ __forceinline__ float2 lds_f2(uint32_t addr) {
    float2 v;
    asm volatile("ld.shared.v2.f32 {%0,%1}, [%2];"
                 : "=f"(v.x), "=f"(v.y) : "r"(addr));
    return v;
}
__device__ __forceinline__ void mma16816(float* c, const uint32_t* a, const uint32_t* b) {
    asm volatile(
        "mma.sync.aligned.m16n8k16.row.col.f32.bf16.bf16.f32 "
        "{%0,%1,%2,%3}, {%4,%5,%6,%7}, {%8,%9}, {%0,%1,%2,%3};"
        : "+f"(c[0]), "+f"(c[1]), "+f"(c[2]), "+f"(c[3])
        : "r"(a[0]), "r"(a[1]), "r"(a[2]), "r"(a[3]), "r"(b[0]), "r"(b[1]));
}

// ---------------------------------------------------------------------------
// Prep centers: fp32 -> bf16 + row squared norms (one row per warp). ~2us.
// ---------------------------------------------------------------------------
__global__ void prep_c_kernel(const float* __restrict__ c) {
    int row = blockIdx.x * 8 + (threadIdx.x >> 5);
    if (row >= NCLU) return;
    int lane = threadIdx.x & 31;
    const float4* sr = (const float4*)(c + (size_t)row * DIM);
    uint2* dr = (uint2*)(g_cb + (size_t)row * DIM);
    float s = 0.f;
    #pragma unroll
    for (int t = 0; t < 4; t++) {
        float4 v = sr[lane + 32 * t];
        s += v.x * v.x + v.y * v.y + v.z * v.z + v.w * v.w;
        union { __nv_bfloat162 h[2]; uint2 u; } pk;
        pk.h[0] = __floats2bfloat162_rn(v.x, v.y);
        pk.h[1] = __floats2bfloat162_rn(v.z, v.w);
        dr[lane + 32 * t] = pk.u;
    }
    #pragma unroll
    for (int o = 16; o; o >>= 1) s += __shfl_xor_sync(0xffffffffu, s, o);
    if (lane == 0) g_c2[row] = s;
}

// ---------------------------------------------------------------------------
// Fused GEMM + t-student epilogue.
// CTA tile 128x256, cluster of 2 CTAs covers the 512 clusters of the same 128
// rows (row sums exchanged via DSMEM). 256 threads, 8 warps (4m x 2n).
// A is consumed as fp32 directly from the input: cp.async fp32 staging ->
// per-lane LDS at mma-fragment coords -> cvt to bf16x2 in registers.
// ||x||^2 accumulated in-register during conversion (exact fp32).
// ---------------------------------------------------------------------------
static constexpr int TM = 128, TN = 256, KC = 64, NUM_KC = DIM / KC;  // 8
static constexpr int ASTB    = TM * KC * 4;            // fp32 A stage: 32768
static constexpr int B_BYTES = TN * KC * 2;            // 32768
static constexpr int A_OFF   = 0;
static constexpr int B_OFF   = 3 * ASTB;               // 98304
static constexpr int C2_OFF  = B_OFF + 3 * B_BYTES;    // 196608
static constexpr int RED_OFF = C2_OFF + NCLU * 4;      // 198656
static constexpr int PEER_OFF = RED_OFF + TM * 2 * 4;  // 199680
static constexpr int INV_OFF  = PEER_OFF + TM * 4;     // 200192
static constexpr int SMEM_TOTAL = INV_OFF + TM * 4;    // 200704

__global__ void __launch_bounds__(256, 1) __cluster_dims__(2, 1, 1)
gemm_kernel(const float* __restrict__ x, float* __restrict__ out) {
    extern __shared__ __align__(1024) char smem[];
    uint32_t sb = smem_to_u32(smem);
    int tid = threadIdx.x;
    int wid = tid >> 5, lane = tid & 31;
    int mtile = blockIdx.x >> 1;
    int nhalf = blockIdx.x & 1;
    int warp_m = wid & 3;        // 4 x 32 rows
    int warp_n = wid >> 2;       // 2 x 128 cols

    float* c2s  = (float*)(smem + C2_OFF);
    float* red  = (float*)(smem + RED_OFF);
    float* peer = (float*)(smem + PEER_OFF);
    float* invs = (float*)(smem + INV_OFF);

    for (int i = tid; i < NCLU; i += 256) c2s[i] = g_c2[i];

    const float* asrc0 = x + (size_t)mtile * TM * DIM;
    const __nv_bfloat16* bsrc0 = g_cb + (size_t)nhalf * TN * DIM;

    auto load_chunk = [&](int kc, int s) {
        uint32_t Ab = sb + A_OFF + s * ASTB;
        uint32_t Bb = sb + B_OFF + s * B_BYTES;
        const float* asrc = asrc0 + kc * KC;
        const __nv_bfloat16* bsrc = bsrc0 + kc * KC;
        #pragma unroll
        for (int i = 0; i < 8; i++) {       // A fp32: 2048 16B chunks
            int idx = tid + i * 256;
            int r = idx >> 4, c = idx & 15;
            cp16(Ab + r * 256 + ((c * 16) ^ ((r & 7) << 4)),
                 asrc + (size_t)r * DIM + c * 4);
        }
        #pragma unroll
        for (int i = 0; i < 8; i++) {       // B bf16: 2048 16B chunks
            int idx = tid + i * 256;
            int r = idx >> 3, c = idx & 7;
            cp16(Bb + r * 128 + ((c * 16) ^ ((r & 7) << 4)),
                 bsrc + (size_t)r * DIM + c * 8);
        }
        cp_commit();
    };

    // B-side ldmatrix addressing (unchanged from R2)
    int ri = lane & 7;
    uint32_t mask  = (uint32_t)ri << 4;
    uint32_t b_row0 = (uint32_t)(warp_n * 128 + (lane >> 4) * 8 + ri) * 128;
    uint32_t bkoff  = (uint32_t)((lane >> 3) & 1) * 16;

    // A-side per-lane fragment LDS addressing:
    // row = warp_m*32 + mt*16 + rh*8 + (lane>>2)
    // col = ks*16 + kh*8 + (lane&3)*2
    // addr = Ast + row*256 + (((col>>2)<<4) ^ ((lane>>2)<<4)) + (col&3)*4
    uint32_t a_swz   = (uint32_t)(lane >> 2) << 4;
    uint32_t a_rbase = (uint32_t)(warp_m * 32 + (lane >> 2)) * 256;
    uint32_t a_cbase = (uint32_t)((((lane & 3) * 2) >> 2) << 4) ^ a_swz;
    uint32_t a_clow  = (uint32_t)((((lane & 3) * 2) & 3) << 2);

    float acc[2][16][4] = {};   // warp tile 32x128
    float xs[2][2] = {};        // ||x||^2 partials: [mt][rh]

    load_chunk(0, 0);
    load_chunk(1, 1);

    for (int kc = 0; kc < NUM_KC; kc++) {
        int s = kc % 3;
        if (kc < NUM_KC - 1) cp_wait<1>(); else cp_wait<0>();
        __syncthreads();
        if (kc + 2 < NUM_KC) load_chunk(kc + 2, (kc + 2) % 3);

        uint32_t Ab = sb + A_OFF + s * ASTB;
        uint32_t Bb = sb + B_OFF + s * B_BYTES;
        #pragma unroll
        for (int ks = 0; ks < 4; ks++) {
            // Convert A fragments fp32 -> bf16x2 and accumulate x^2
            uint32_t a[2][4];
            #pragma unroll
            for (int mt = 0; mt < 2; mt++) {
                #pragma unroll
                for (int j = 0; j < 4; j++) {
                    int rh = j & 1, kh = j >> 1;
                    uint32_t ad = Ab + a_rbase + (uint32_t)(mt * 16 + rh * 8) * 256
                                + ((a_cbase ^ (uint32_t)((ks * 4 + kh * 2) << 4)))
                                + a_clow;
                    float2 v = lds_f2(ad);
                    xs[mt][rh] += v.x * v.x + v.y * v.y;
                    union { __nv_bfloat162 h; uint32_t u; } pk;
                    pk.h = __floats2bfloat162_rn(v.x, v.y);
                    a[mt][j] = pk.u;
                }
            }
            // B fragments via ldmatrix
            uint32_t b[32];
            uint32_t bkb = (bkoff + ks * 32) ^ mask;
            #pragma unroll
            for (int gg = 0; gg < 8; gg++)
                ldsm4(b + gg * 4, Bb + b_row0 + gg * 2048 + bkb);
            #pragma unroll
            for (int mt = 0; mt < 2; mt++)
                #pragma unroll
                for (int nt = 0; nt < 16; nt++)
                    mma16816(acc[mt][nt], a[mt], b + nt * 2);
        }
    }

    // ---------------- Epilogue ----------------
    // Finish ||x||^2: quad reduce (cols are spread over the 4 lanes of a quad)
    #pragma unroll
    for (int mt = 0; mt < 2; mt++)
        #pragma unroll
        for (int h = 0; h < 2; h++) {
            xs[mt][h] += __shfl_xor_sync(0xffffffffu, xs[mt][h], 1);
            xs[mt][h] += __shfl_xor_sync(0xffffffffu, xs[mt][h], 2);
        }

    int g = lane >> 2, qa = lane & 3;
    float rs[2][2];
    #pragma unroll
    for (int mt = 0; mt < 2; mt++) {
        #pragma unroll
        for (int h = 0; h < 2; h++) {
            float x2v = xs[mt][h];
            float p = 0.f;
            #pragma unroll
            for (int nt = 0; nt < 16; nt++) {
                int col = nhalf * 256 + warp_n * 128 + nt * 8 + qa * 2;
                float b0 = x2v + c2s[col];
                float b1 = x2v + c2s[col + 1];
                float q0 = frcp(1.f + fmaxf(fmaf(-2.f, acc[mt][nt][h * 2 + 0], b0), 0.f));
                float q1 = frcp(1.f + fmaxf(fmaf(-2.f, acc[mt][nt][h * 2 + 1], b1), 0.f));
                acc[mt][nt][h * 2 + 0] = q0;
                acc[mt][nt][h * 2 + 1] = q1;
                p += q0 + q1;
            }
            rs[mt][h] = p;
        }
    }
    #pragma unroll
    for (int mt = 0; mt < 2; mt++)
        #pragma unroll
        for (int h = 0; h < 2; h++) {
            rs[mt][h] += __shfl_xor_sync(0xffffffffu, rs[mt][h], 1);
            rs[mt][h] += __shfl_xor_sync(0xffffffffu, rs[mt][h], 2);
        }
    if (qa == 0) {
        #pragma unroll
        for (int mt = 0; mt < 2; mt++)
            #pragma unroll
            for (int h = 0; h < 2; h++)
                red[(warp_m * 32 + mt * 16 + h * 8 + g) * 2 + warp_n] = rs[mt][h];
    }
    __syncthreads();

    float L = 0.f;
    if (tid < TM) {
        L = red[tid * 2] + red[tid * 2 + 1];
        uint32_t paddr;
        asm volatile("mapa.shared::cluster.u32 %0, %1, %2;"
                     : "=r"(paddr) : "r"(sb + PEER_OFF + tid * 4), "r"(nhalf ^ 1));
        asm volatile("st.shared::cluster.f32 [%0], %1;" :: "r"(paddr), "f"(L) : "memory");
    }
    asm volatile("barrier.cluster.arrive.aligned;" ::: "memory");
    asm volatile("barrier.cluster.wait.aligned;" ::: "memory");
    if (tid < TM) invs[tid] = frcp(L + peer[tid]);
    __syncthreads();

    float* outbase = out + (size_t)mtile * TM * NCLU + nhalf * TN;
    #pragma unroll
    for (int mt = 0; mt < 2; mt++) {
        #pragma unroll
        for (int h = 0; h < 2; h++) {
            int row = warp_m * 32 + mt * 16 + h * 8 + g;
            float inv = invs[row];
            float* orow = outbase + (size_t)row * NCLU + warp_n * 128;
            #pragma unroll
            for (int nt = 0; nt < 16; nt++) {
                float2 v;
                v.x = acc[mt][nt][h * 2 + 0] * inv;
                v.y = acc[mt][nt][h * 2 + 1] * inv;
                *(float2*)(orow + nt * 8 + qa * 2) = v;
            }
        }
    }
}

// ---------------------------------------------------------------------------
// Launch
// ---------------------------------------------------------------------------
extern "C" void kernel_launch(void* const* d_in, const int* in_sizes, int n_in,
                              void* d_out, int out_size) {
    const float* x  = (const float*)d_in[0];
    const float* cc = (const float*)d_in[1];
    float* out = (float*)d_out;

    cudaFuncSetAttribute(gemm_kernel,
                         cudaFuncAttributeMaxDynamicSharedMemorySize, SMEM_TOTAL);

    prep_c_kernel<<<NCLU / 8, 256>>>(cc);
    gemm_kernel<<<(N_ROWS / TM) * 2, 256, SMEM_TOTAL>>>(x, out);
}

// round 4
// speedup vs baseline: 1.0383x; 1.0119x over previous
#include <cuda_runtime.h>
#include <cuda_bf16.h>
#include <cstdint>
#include <cstddef>

#define N_ROWS 131072
#define DIM    512
#define NCLU   512

// ---------------------------------------------------------------------------
// Device-global scratch (centers only)
// ---------------------------------------------------------------------------
__device__ __nv_bfloat16 g_cb[(size_t)NCLU * DIM];
__device__ float g_c2[NCLU];

// ---------------------------------------------------------------------------
// Helpers (base ISA only)
// ---------------------------------------------------------------------------
__device__ __forceinline__ uint32_t smem_to_u32(const void* smem_ptr) {
    uint32_t addr;
    asm("{ .reg .u64 tmp; cvta.to.shared.u64 tmp, %1; cvt.u32.u64 %0, tmp; }"
        : "=r"(addr) : "l"(smem_ptr));
    return addr;
}
__device__ __forceinline__ void cp16(uint32_t dst_smem, const void* src) {
    asm volatile("cp.async.cg.shared.global [%0], [%1], 16;"
                 :: "r"(dst_smem), "l"(src));
}
__device__ __forceinline__ void cp_commit() {
    asm volatile("cp.async.commit_group;");
}
template <int N>
__device__ __forceinline__ void cp_wait() {
    asm volatile("cp.async.wait_group %0;" :: "n"(N));
}
__device__ __forceinline__ float frcp(float a) {
    float r;
    asm("rcp.approx.f32 %0, %1;" : "=f"(r) : "f"(a));
    return r;
}
__device__ __forceinline__ void ldsm4(uint32_t* r, uint32_t addr) {
    asm volatile("ldmatrix.sync.aligned.m8n8.x4.shared.b16 {%0,%1,%2,%3}, [%4];"
                 : "=r"(r[0]), "=r"(r[1]), "=r"(r[2]), "=r"(r[3]) : "r"(addr));
}
__device__ __forceinline__ float4 lds_f4(uint32_t addr) {
    float4 v;
    asm volatile("ld.shared.v4.f32 {%0,%1,%2,%3}, [%4];"
                 : "=f"(v.x), "=f"(v.y), "=f"(v.z), "=f"(v.w) : "r"(addr));
    return v;
}
__device__ __forceinline__ void sts_v4(uint32_t addr, uint32_t a, uint32_t b,
                                       uint32_t c, uint32_t d) {
    asm volatile("st.shared.v4.b32 [%0], {%1,%2,%3,%4};"
                 :: "r"(addr), "r"(a), "r"(b), "r"(c), "r"(d) : "memory");
}
__device__ __forceinline__ void mma16816(float* c, const uint32_t* a, const uint32_t* b) {
    asm volatile(
        "mma.sync.aligned.m16n8k16.row.col.f32.bf16.bf16.f32 "
        "{%0,%1,%2,%3}, {%4,%5,%6,%7}, {%8,%9}, {%0,%1,%2,%3};"
        : "+f"(c[0]), "+f"(c[1]), "+f"(c[2]), "+f"(c[3])
        : "r"(a[0]), "r"(a[1]), "r"(a[2]), "r"(a[3]), "r"(b[0]), "r"(b[1]));
}
__device__ __forceinline__ uint32_t pack_bf16(float a, float b) {
    union { __nv_bfloat162 h; uint32_t u; } pk;
    pk.h = __floats2bfloat162_rn(a, b);
    return pk.u;
}

// ---------------------------------------------------------------------------
// Prep centers: fp32 -> bf16 + row norms (one row per warp). ~2us.
// ---------------------------------------------------------------------------
__global__ void prep_c_kernel(const float* __restrict__ c) {
    int row = blockIdx.x * 8 + (threadIdx.x >> 5);
    if (row >= NCLU) return;
    int lane = threadIdx.x & 31;
    const float4* sr = (const float4*)(c + (size_t)row * DIM);
    uint2* dr = (uint2*)(g_cb + (size_t)row * DIM);
    float s = 0.f;
    #pragma unroll
    for (int t = 0; t < 4; t++) {
        float4 v = sr[lane + 32 * t];
        s += v.x * v.x + v.y * v.y + v.z * v.z + v.w * v.w;
        union { __nv_bfloat162 h[2]; uint2 u; } pk;
        pk.h[0] = __floats2bfloat162_rn(v.x, v.y);
        pk.h[1] = __floats2bfloat162_rn(v.z, v.w);
        dr[lane + 32 * t] = pk.u;
    }
    #pragma unroll
    for (int o = 16; o; o >>= 1) s += __shfl_xor_sync(0xffffffffu, s, o);
    if (lane == 0) g_c2[row] = s;
}

// ---------------------------------------------------------------------------
// Fused GEMM + t-student epilogue. 512 threads, 16 warps (4m x 4n),
// warp tile 32x64. CTA tile 128x256; cluster of 2 CTAs = full 512 clusters.
// A: cp.async fp32 staging -> bulk convert pass to bf16 smem (once per kc,
// accumulating ||x||^2 exactly) -> ldmatrix. B: bf16 via ldmatrix.
// ---------------------------------------------------------------------------
static constexpr int TM = 128, TN = 256, KC = 64, NUM_KC = DIM / KC;  // 8
static constexpr int AF_BYTES = TM * KC * 4;            // 32768 per stage
static constexpr int ABF_BYTES = TM * KC * 2;           // 16384
static constexpr int B_BYTES  = TN * KC * 2;            // 32768 per stage
static constexpr int AF_OFF   = 0;                      // 2 stages
static constexpr int ABF_OFF  = 2 * AF_BYTES;           // 65536
static constexpr int B_OFF    = ABF_OFF + ABF_BYTES;    // 81920, 2 stages
static constexpr int C2_OFF   = B_OFF + 2 * B_BYTES;    // 147456
static constexpr int X2_OFF   = C2_OFF + NCLU * 4;      // 149504
static constexpr int RED_OFF  = X2_OFF + TM * 4;        // 150016 (128 x 4)
static constexpr int PEER_OFF = RED_OFF + TM * 4 * 4;   // 152064
static constexpr int INV_OFF  = PEER_OFF + TM * 4;      // 152576
static constexpr int SMEM_TOTAL = INV_OFF + TM * 4;     // 153088

__global__ void __launch_bounds__(512, 1) __cluster_dims__(2, 1, 1)
gemm_kernel(const float* __restrict__ x, float* __restrict__ out) {
    extern __shared__ __align__(1024) char smem[];
    uint32_t sb = smem_to_u32(smem);
    int tid = threadIdx.x;
    int wid = tid >> 5, lane = tid & 31;
    int mtile = blockIdx.x >> 1;
    int nhalf = blockIdx.x & 1;
    int warp_m = wid & 3;        // 4 x 32 rows
    int warp_n = wid >> 2;       // 4 x 64 cols

    float* c2s  = (float*)(smem + C2_OFF);
    float* x2s  = (float*)(smem + X2_OFF);
    float* red  = (float*)(smem + RED_OFF);
    float* peer = (float*)(smem + PEER_OFF);
    float* invs = (float*)(smem + INV_OFF);

    for (int i = tid; i < NCLU; i += 512) c2s[i] = g_c2[i];

    const float* asrc0 = x + (size_t)mtile * TM * DIM;
    const __nv_bfloat16* bsrc0 = g_cb + (size_t)nhalf * TN * DIM;

    auto load_chunk = [&](int kc, int s) {
        uint32_t Af = sb + AF_OFF + s * AF_BYTES;
        uint32_t Bb = sb + B_OFF + s * B_BYTES;
        const float* asrc = asrc0 + kc * KC;
        const __nv_bfloat16* bsrc = bsrc0 + kc * KC;
        #pragma unroll
        for (int i = 0; i < 4; i++) {       // A fp32: 2048 16B chunks
            int idx = tid + i * 512;
            int r = idx >> 4, c = idx & 15;
            cp16(Af + r * 256 + ((c * 16) ^ ((r & 7) << 4)),
                 asrc + (size_t)r * DIM + c * 4);
        }
        #pragma unroll
        for (int i = 0; i < 4; i++) {       // B bf16: 2048 16B chunks
            int idx = tid + i * 512;
            int r = idx >> 3, c = idx & 7;
            cp16(Bb + r * 128 + ((c * 16) ^ ((r & 7) << 4)),
                 bsrc + (size_t)r * DIM + c * 8);
        }
        cp_commit();
    };

    // ldmatrix lane addressing
    int ri = lane & 7;
    uint32_t mask = (uint32_t)ri << 4;
    // A (Abf, 128B rows): row = warp_m*32 + mt*16 + ((lane>>3)&1)*8 + ri
    uint32_t a_row0 = (uint32_t)(warp_m * 32 + ((lane >> 3) & 1) * 8 + ri) * 128;
    uint32_t akoff  = (uint32_t)(lane >> 4) * 16;
    // B (128B rows): row = warp_n*64 + gg*16 + (lane>>4)*8 + ri
    uint32_t b_row0 = (uint32_t)(warp_n * 64 + (lane >> 4) * 8 + ri) * 128;
    uint32_t bkoff  = (uint32_t)((lane >> 3) & 1) * 16;

    // Convert-pass addressing: row = tid>>2, seg = tid&3 (16 elems each)
    uint32_t crow = (uint32_t)(tid >> 2), cseg = (uint32_t)(tid & 3);
    uint32_t cswz = (crow & 7) << 4;

    float acc[2][8][4] = {};   // warp tile 32x64
    float xacc = 0.f;          // ||x||^2 partial (16 elems/kc, row = tid>>2)

    load_chunk(0, 0);

    for (int kc = 0; kc < NUM_KC; kc++) {
        int s = kc & 1;
        cp_wait<0>();
        __syncthreads();
        if (kc + 1 < NUM_KC) load_chunk(kc + 1, s ^ 1);

        // ---- Convert A fp32 -> bf16 smem (each element once per CTA) ----
        {
            uint32_t Af = sb + AF_OFF + s * AF_BYTES + crow * 256;
            float4 v[4];
            #pragma unroll
            for (int i = 0; i < 4; i++) {
                uint32_t c = cseg * 4 + i;
                v[i] = lds_f4(Af + ((c * 16) ^ cswz));
            }
            #pragma unroll
            for (int i = 0; i < 4; i++)
                xacc += v[i].x * v[i].x + v[i].y * v[i].y
                      + v[i].z * v[i].z + v[i].w * v[i].w;
            uint32_t Ab = sb + ABF_OFF + crow * 128;
            sts_v4(Ab + (((cseg * 2 + 0) * 16) ^ cswz),
                   pack_bf16(v[0].x, v[0].y), pack_bf16(v[0].z, v[0].w),
                   pack_bf16(v[1].x, v[1].y), pack_bf16(v[1].z, v[1].w));
            sts_v4(Ab + (((cseg * 2 + 1) * 16) ^ cswz),
                   pack_bf16(v[2].x, v[2].y), pack_bf16(v[2].z, v[2].w),
                   pack_bf16(v[3].x, v[3].y), pack_bf16(v[3].z, v[3].w));
        }
        __syncthreads();

        // ---- MMA over this k-chunk ----
        uint32_t Ab = sb + ABF_OFF;
        uint32_t Bb = sb + B_OFF + s * B_BYTES;
        #pragma unroll
        for (int ks = 0; ks < 4; ks++) {
            uint32_t a[2][4], b[16];
            uint32_t akb = (akoff + ks * 32) ^ mask;
            uint32_t bkb = (bkoff + ks * 32) ^ mask;
            ldsm4(a[0], Ab + a_row0 + akb);
            ldsm4(a[1], Ab + a_row0 + 2048 + akb);
            #pragma unroll
            for (int gg = 0; gg < 4; gg++)
                ldsm4(b + gg * 4, Bb + b_row0 + gg * 2048 + bkb);
            #pragma unroll
            for (int mt = 0; mt < 2; mt++)
                #pragma unroll
                for (int nt = 0; nt < 8; nt++)
                    mma16816(acc[mt][nt], a[mt], b + nt * 2);
        }
    }

    // ---------------- Epilogue ----------------
    // ||x||^2: 4 threads per row share a warp quad -> shfl reduce, store.
    xacc += __shfl_xor_sync(0xffffffffu, xacc, 1);
    xacc += __shfl_xor_sync(0xffffffffu, xacc, 2);
    if ((lane & 3) == 0) x2s[tid >> 2] = xacc;
    __syncthreads();

    int g = lane >> 2, qa = lane & 3;
    float rs[2][2];
    #pragma unroll
    for (int mt = 0; mt < 2; mt++) {
        #pragma unroll
        for (int h = 0; h < 2; h++) {
            int row = warp_m * 32 + mt * 16 + h * 8 + g;
            float x2v = x2s[row];
            float p = 0.f;
            #pragma unroll
            for (int nt = 0; nt < 8; nt++) {
                int col = nhalf * 256 + warp_n * 64 + nt * 8 + qa * 2;
                float b0 = x2v + c2s[col];
                float b1 = x2v + c2s[col + 1];
                float q0 = frcp(1.f + fmaxf(fmaf(-2.f, acc[mt][nt][h * 2 + 0], b0), 0.f));
                float q1 = frcp(1.f + fmaxf(fmaf(-2.f, acc[mt][nt][h * 2 + 1], b1), 0.f));
                acc[mt][nt][h * 2 + 0] = q0;
                acc[mt][nt][h * 2 + 1] = q1;
                p += q0 + q1;
            }
            rs[mt][h] = p;
        }
    }
    #pragma unroll
    for (int mt = 0; mt < 2; mt++)
        #pragma unroll
        for (int h = 0; h < 2; h++) {
            rs[mt][h] += __shfl_xor_sync(0xffffffffu, rs[mt][h], 1);
            rs[mt][h] += __shfl_xor_sync(0xffffffffu, rs[mt][h], 2);
        }
    if (qa == 0) {
        #pragma unroll
        for (int mt = 0; mt < 2; mt++)
            #pragma unroll
            for (int h = 0; h < 2; h++)
                red[(warp_m * 32 + mt * 16 + h * 8 + g) * 4 + warp_n] = rs[mt][h];
    }
    __syncthreads();

    float L = 0.f;
    if (tid < TM) {
        L = red[tid * 4] + red[tid * 4 + 1] + red[tid * 4 + 2] + red[tid * 4 + 3];
        uint32_t paddr;
        asm volatile("mapa.shared::cluster.u32 %0, %1, %2;"
                     : "=r"(paddr) : "r"(sb + PEER_OFF + tid * 4), "r"(nhalf ^ 1));
        asm volatile("st.shared::cluster.f32 [%0], %1;" :: "r"(paddr), "f"(L) : "memory");
    }
    asm volatile("barrier.cluster.arrive.aligned;" ::: "memory");
    asm volatile("barrier.cluster.wait.aligned;" ::: "memory");
    if (tid < TM) invs[tid] = frcp(L + peer[tid]);
    __syncthreads();

    float* outbase = out + (size_t)mtile * TM * NCLU + nhalf * TN;
    #pragma unroll
    for (int mt = 0; mt < 2; mt++) {
        #pragma unroll
        for (int h = 0; h < 2; h++) {
            int row = warp_m * 32 + mt * 16 + h * 8 + g;
            float inv = invs[row];
            float* orow = outbase + (size_t)row * NCLU + warp_n * 64;
            #pragma unroll
            for (int nt = 0; nt < 8; nt++) {
                float2 v;
                v.x = acc[mt][nt][h * 2 + 0] * inv;
                v.y = acc[mt][nt][h * 2 + 1] * inv;
                *(float2*)(orow + nt * 8 + qa * 2) = v;
            }
        }
    }
}

// ---------------------------------------------------------------------------
// Launch
// ---------------------------------------------------------------------------
extern "C" void kernel_launch(void* const* d_in, const int* in_sizes, int n_in,
                              void* d_out, int out_size) {
    const float* x  = (const float*)d_in[0];
    const float* cc = (const float*)d_in[1];
    float* out = (float*)d_out;

    cudaFuncSetAttribute(gemm_kernel,
                         cudaFuncAttributeMaxDynamicSharedMemorySize, SMEM_TOTAL);

    prep_c_kernel<<<NCLU / 8, 256>>>(cc);
    gemm_kernel<<<(N_ROWS / TM) * 2, 512, SMEM_TOTAL>>>(x, out);
}

// round 6
// speedup vs baseline: 1.0789x; 1.0391x over previous
#include <cuda_runtime.h>
#include <cuda_bf16.h>
#include <cstdint>
#include <cstddef>

#define N_ROWS 131072
#define DIM    512
#define NCLU   512

// ---------------------------------------------------------------------------
// Device-global scratch (centers only)
// ---------------------------------------------------------------------------
__device__ __nv_bfloat16 g_cb[(size_t)NCLU * DIM];
__device__ float g_c2[NCLU];

// ---------------------------------------------------------------------------
// Helpers (base ISA only)
// ---------------------------------------------------------------------------
__device__ __forceinline__ uint32_t smem_to_u32(const void* smem_ptr) {
    uint32_t addr;
    asm("{ .reg .u64 tmp; cvta.to.shared.u64 tmp, %1; cvt.u32.u64 %0, tmp; }"
        : "=r"(addr) : "l"(smem_ptr));
    return addr;
}
__device__ __forceinline__ void cp16(uint32_t dst_smem, const void* src) {
    asm volatile("cp.async.cg.shared.global [%0], [%1], 16;"
                 :: "r"(dst_smem), "l"(src));
}
__device__ __forceinline__ void cp_commit() {
    asm volatile("cp.async.commit_group;");
}
template <int N>
__device__ __forceinline__ void cp_wait() {
    asm volatile("cp.async.wait_group %0;" :: "n"(N));
}
__device__ __forceinline__ float frcp(float a) {
    float r;
    asm("rcp.approx.f32 %0, %1;" : "=f"(r) : "f"(a));
    return r;
}
__device__ __forceinline__ void ldsm4(uint32_t* r, uint32_t addr) {
    asm volatile("ldmatrix.sync.aligned.m8n8.x4.shared.b16 {%0,%1,%2,%3}, [%4];"
                 : "=r"(r[0]), "=r"(r[1]), "=r"(r[2]), "=r"(r[3]) : "r"(addr));
}
__device__ __forceinline__ float4 lds_f4(uint32_t addr) {
    float4 v;
    asm volatile("ld.shared.v4.f32 {%0,%1,%2,%3}, [%4];"
                 : "=f"(v.x), "=f"(v.y), "=f"(v.z), "=f"(v.w) : "r"(addr));
    return v;
}
__device__ __forceinline__ void sts_v2(uint32_t addr, uint32_t a, uint32_t b) {
    asm volatile("st.shared.v2.b32 [%0], {%1,%2};"
                 :: "r"(addr), "r"(a), "r"(b) : "memory");
}
__device__ __forceinline__ void mma16816(float* c, const uint32_t* a, const uint32_t* b) {
    asm volatile(
        "mma.sync.aligned.m16n8k16.row.col.f32.bf16.bf16.f32 "
        "{%0,%1,%2,%3}, {%4,%5,%6,%7}, {%8,%9}, {%0,%1,%2,%3};"
        : "+f"(c[0]), "+f"(c[1]), "+f"(c[2]), "+f"(c[3])
        : "r"(a[0]), "r"(a[1]), "r"(a[2]), "r"(a[3]), "r"(b[0]), "r"(b[1]));
}
__device__ __forceinline__ uint32_t pack_bf16(float a, float b) {
    union { __nv_bfloat162 h; uint32_t u; } pk;
    pk.h = __floats2bfloat162_rn(a, b);
    return pk.u;
}

// ---------------------------------------------------------------------------
// Prep centers: fp32 -> bf16 + row norms (one row per warp). ~2us.
// ---------------------------------------------------------------------------
__global__ void prep_c_kernel(const float* __restrict__ c) {
    int row = blockIdx.x * 8 + (threadIdx.x >> 5);
    if (row >= NCLU) return;
    int lane = threadIdx.x & 31;
    const float4* sr = (const float4*)(c + (size_t)row * DIM);
    uint2* dr = (uint2*)(g_cb + (size_t)row * DIM);
    float s = 0.f;
    #pragma unroll
    for (int t = 0; t < 4; t++) {
        float4 v = sr[lane + 32 * t];
        s += v.x * v.x + v.y * v.y + v.z * v.z + v.w * v.w;
        union { __nv_bfloat162 h[2]; uint2 u; } pk;
        pk.h[0] = __floats2bfloat162_rn(v.x, v.y);
        pk.h[1] = __floats2bfloat162_rn(v.z, v.w);
        dr[lane + 32 * t] = pk.u;
    }
    #pragma unroll
    for (int o = 16; o; o >>= 1) s += __shfl_xor_sync(0xffffffffu, s, o);
    if (lane == 0) g_c2[row] = s;
}

// ---------------------------------------------------------------------------
// Fused GEMM + t-student epilogue. 256 threads, 8 warps (2m x 4n), warp tile
// 64x64. CTA tile 128x256; cluster of 2 covers 512 clusters.
// A fp32 staged via cp.async; fp32->bf16 convert is double-buffered and
// overlapped with MMA (each thread converts only its own cp.async'd bytes,
// so no barrier before convert). One __syncthreads per k-chunk.
// ---------------------------------------------------------------------------
static constexpr int TM = 128, TN = 256, KC = 64, NUM_KC = DIM / KC;  // 8
static constexpr int AF_BYTES  = TM * KC * 4;            // 32768 / stage
static constexpr int ABF_BYTES = TM * KC * 2;            // 16384 / buf
static constexpr int B_BYTES   = TN * KC * 2;            // 32768 / stage
static constexpr int AF_OFF   = 0;                        // 2 stages
static constexpr int ABF_OFF  = 2 * AF_BYTES;             // 65536, 2 bufs
static constexpr int B_OFF    = ABF_OFF + 2 * ABF_BYTES;  // 98304, 2 stages
static constexpr int C2_OFF   = B_OFF + 2 * B_BYTES;      // 163840
static constexpr int X2P_OFF  = C2_OFF + NCLU * 4;        // 165888 (128x16 f32)
static constexpr int X2_OFF   = X2P_OFF + TM * 16 * 4;    // 174080
static constexpr int RED_OFF  = X2_OFF + TM * 4;          // 174592 (128x4)
static constexpr int PEER_OFF = RED_OFF + TM * 4 * 4;     // 176640
static constexpr int INV_OFF  = PEER_OFF + TM * 4;        // 177152
static constexpr int SMEM_TOTAL = INV_OFF + TM * 4;       // 177664

__global__ void __launch_bounds__(256, 1) __cluster_dims__(2, 1, 1)
gemm_kernel(const float* __restrict__ x, float* __restrict__ out) {
    extern __shared__ __align__(1024) char smem[];
    uint32_t sb = smem_to_u32(smem);
    int tid = threadIdx.x;
    int wid = tid >> 5, lane = tid & 31;
    int mtile = blockIdx.x >> 1;
    int nhalf = blockIdx.x & 1;
    int warp_m = wid & 1;        // 2 x 64 rows
    int warp_n = wid >> 1;       // 4 x 64 cols

    float* c2s  = (float*)(smem + C2_OFF);
    float* x2p  = (float*)(smem + X2P_OFF);
    float* x2s  = (float*)(smem + X2_OFF);
    float* red  = (float*)(smem + RED_OFF);
    float* peer = (float*)(smem + PEER_OFF);
    float* invs = (float*)(smem + INV_OFF);

    for (int i = tid; i < NCLU; i += 256) c2s[i] = g_c2[i];

    const float* asrc0 = x + (size_t)mtile * TM * DIM;
    const __nv_bfloat16* bsrc0 = g_cb + (size_t)nhalf * TN * DIM;

    // A chunk ownership: thread owns chunks idx = tid + i*256, i=0..7
    //   -> row = (tid>>4) + 16*i, cpos = tid&15  (fixed across kc)
    int r0 = tid >> 4, cpos = tid & 15;

    auto load_A = [&](int kc, int s) {
        uint32_t Af = sb + AF_OFF + s * AF_BYTES;
        const float* asrc = asrc0 + kc * KC;
        #pragma unroll
        for (int i = 0; i < 8; i++) {
            int r = r0 + i * 16;
            cp16(Af + r * 256 + ((cpos * 16) ^ ((r & 7) << 4)),
                 asrc + (size_t)r * DIM + cpos * 4);
        }
        cp_commit();
    };
    auto load_B = [&](int kc, int s) {
        uint32_t Bb = sb + B_OFF + s * B_BYTES;
        const __nv_bfloat16* bsrc = bsrc0 + kc * KC;
        #pragma unroll
        for (int i = 0; i < 8; i++) {
            int idx = tid + i * 256;
            int r = idx >> 3, c = idx & 7;
            cp16(Bb + r * 128 + ((c * 16) ^ ((r & 7) << 4)),
                 bsrc + (size_t)r * DIM + c * 8);
        }
        cp_commit();
    };

    float xpart[8] = {};  // ||x||^2 partials for rows r0+16i, elems cpos*4..+3 per kc

    // Convert own chunks of AF[sf] -> Abf[bf] (bf16, SW128), accumulate x^2.
    auto convert = [&](int sf, int bf) {
        uint32_t Af = sb + AF_OFF + sf * AF_BYTES;
        uint32_t Ab = sb + ABF_OFF + bf * ABF_BYTES;
        #pragma unroll
        for (int i = 0; i < 8; i++) {
            int r = r0 + i * 16;
            uint32_t swz = (uint32_t)(r & 7) << 4;
            float4 v = lds_f4(Af + r * 256 + ((cpos * 16) ^ swz));
            xpart[i] += v.x * v.x + v.y * v.y + v.z * v.z + v.w * v.w;
            sts_v2(Ab + r * 128 + (((cpos >> 1) * 16) ^ swz) + (cpos & 1) * 8,
                   pack_bf16(v.x, v.y), pack_bf16(v.z, v.w));
        }
    };

    // ldmatrix lane addressing
    int ri = lane & 7;
    uint32_t mask = (uint32_t)ri << 4;
    // A (Abf, 128B rows): row = warp_m*64 + mt*16 + ((lane>>3)&1)*8 + ri
    uint32_t a_row0 = (uint32_t)(warp_m * 64 + ((lane >> 3) & 1) * 8 + ri) * 128;
    uint32_t akoff  = (uint32_t)(lane >> 4) * 16;
    // B (128B rows): row = warp_n*64 + gg*16 + (lane>>4)*8 + ri
    uint32_t b_row0 = (uint32_t)(warp_n * 64 + (lane >> 4) * 8 + ri) * 128;
    uint32_t bkoff  = (uint32_t)((lane >> 3) & 1) * 16;

    float acc[4][8][4] = {};   // warp tile 64x64: 4 m16 x 8 n8

    // ---- Prologue ----
    load_A(0, 0); load_B(0, 0);       // groups: A0, B0
    cp_wait<1>();                     // A0 done (self-visible)
    convert(0, 0);
    load_A(1, 1); load_B(1, 1);       // outstanding: B0, A1, B1
    cp_wait<2>();                     // B0 done
    __syncthreads();                  // B0 + Abf0 visible to all

    for (int kc = 0; kc < NUM_KC; kc++) {
        int s = kc & 1;
        uint32_t Ab = sb + ABF_OFF + s * ABF_BYTES;
        uint32_t Bb = sb + B_OFF + s * B_BYTES;

        #pragma unroll
        for (int ks = 0; ks < 4; ks++) {
            if (ks == 2 && kc < NUM_KC - 1) {
                cp_wait<1>();                       // A[kc+1] done (self)
                convert(s ^ 1, s ^ 1);              // overlap with remaining mma
            }
            uint32_t a[4][4], b[4][4];
            uint32_t akb = (akoff + ks * 32) ^ mask;
            uint32_t bkb = (bkoff + ks * 32) ^ mask;
            #pragma unroll
            for (int mt = 0; mt < 4; mt++)
                ldsm4(a[mt], Ab + a_row0 + (uint32_t)(mt * 2048) + akb);
            #pragma unroll
            for (int gg = 0; gg < 4; gg++)
                ldsm4(b[gg], Bb + b_row0 + (uint32_t)(gg * 2048) + bkb);
            #pragma unroll
            for (int mt = 0; mt < 4; mt++)
                #pragma unroll
                for (int nt = 0; nt < 8; nt++)
                    mma16816(acc[mt][nt], a[mt], b[nt >> 1] + (nt & 1) * 2);
        }

        if (kc < NUM_KC - 1) cp_wait<0>();          // B[kc+1] done
        __syncthreads();                            // publish Abf[s^1], B[kc+1]
        if (kc + 2 < NUM_KC) { load_A(kc + 2, s); load_B(kc + 2, s); }
    }

    // ---------------- Epilogue ----------------
    // ||x||^2: partials -> smem matrix -> per-row sum
    #pragma unroll
    for (int i = 0; i < 8; i++) x2p[(r0 + i * 16) * 16 + cpos] = xpart[i];
    __syncthreads();
    if (tid < TM) {
        float s = 0.f;
        #pragma unroll
        for (int j = 0; j < 16; j++) s += x2p[tid * 16 + j];
        x2s[tid] = s;
    }
    __syncthreads();

    int g = lane >> 2, qa = lane & 3;
    float rs[4][2];
    #pragma unroll
    for (int mt = 0; mt < 4; mt++) {
        #pragma unroll
        for (int h = 0; h < 2; h++) {
            int row = warp_m * 64 + mt * 16 + h * 8 + g;
            float x2v = x2s[row];
            float p = 0.f;
            #pragma unroll
            for (int nt = 0; nt < 8; nt++) {
                int col = nhalf * 256 + warp_n * 64 + nt * 8 + qa * 2;
                float b0 = x2v + c2s[col];
                float b1 = x2v + c2s[col + 1];
                float q0 = frcp(1.f + fmaxf(fmaf(-2.f, acc[mt][nt][h * 2 + 0], b0), 0.f));
                float q1 = frcp(1.f + fmaxf(fmaf(-2.f, acc[mt][nt][h * 2 + 1], b1), 0.f));
                acc[mt][nt][h * 2 + 0] = q0;
                acc[mt][nt][h * 2 + 1] = q1;
                p += q0 + q1;
            }
            rs[mt][h] = p;
        }
    }
    #pragma unroll
    for (int mt = 0; mt < 4; mt++)
        #pragma unroll
        for (int h = 0; h < 2; h++) {
            rs[mt][h] += __shfl_xor_sync(0xffffffffu, rs[mt][h], 1);
            rs[mt][h] += __shfl_xor_sync(0xffffffffu, rs[mt][h], 2);
        }
    if (qa == 0) {
        #pragma unroll
        for (int mt = 0; mt < 4; mt++)
            #pragma unroll
            for (int h = 0; h < 2; h++)
                red[(warp_m * 64 + mt * 16 + h * 8 + g) * 4 + warp_n] = rs[mt][h];
    }
    __syncthreads();

    float L = 0.f;
    if (tid < TM) {
        L = red[tid * 4] + red[tid * 4 + 1] + red[tid * 4 + 2] + red[tid * 4 + 3];
        uint32_t paddr;
        asm volatile("mapa.shared::cluster.u32 %0, %1, %2;"
                     : "=r"(paddr) : "r"(sb + PEER_OFF + tid * 4), "r"(nhalf ^ 1));
        asm volatile("st.shared::cluster.f32 [%0], %1;" :: "r"(paddr), "f"(L) : "memory");
    }
    asm volatile("barrier.cluster.arrive.aligned;" ::: "memory");
    asm volatile("barrier.cluster.wait.aligned;" ::: "memory");
    if (tid < TM) invs[tid] = frcp(L + peer[tid]);
    __syncthreads();

    float* outbase = out + (size_t)mtile * TM * NCLU + nhalf * TN;
    #pragma unroll
    for (int mt = 0; mt < 4; mt++) {
        #pragma unroll
        for (int h = 0; h < 2; h++) {
            int row = warp_m * 64 + mt * 16 + h * 8 + g;
            float inv = invs[row];
            float* orow = outbase + (size_t)row * NCLU + warp_n * 64;
            #pragma unroll
            for (int nt = 0; nt < 8; nt++) {
                float2 v;
                v.x = acc[mt][nt][h * 2 + 0] * inv;
                v.y = acc[mt][nt][h * 2 + 1] * inv;
                *(float2*)(orow + nt * 8 + qa * 2) = v;
            }
        }
    }
}

// ---------------------------------------------------------------------------
// Launch
// ---------------------------------------------------------------------------
extern "C" void kernel_launch(void* const* d_in, const int* in_sizes, int n_in,
                              void* d_out, int out_size) {
    const float* x  = (const float*)d_in[0];
    const float* cc = (const float*)d_in[1];
    float* out = (float*)d_out;

    cudaFuncSetAttribute(gemm_kernel,
                         cudaFuncAttributeMaxDynamicSharedMemorySize, SMEM_TOTAL);

    prep_c_kernel<<<NCLU / 8, 256>>>(cc);
    gemm_kernel<<<(N_ROWS / TM) * 2, 256, SMEM_TOTAL>>>(x, out);
}

// round 8
// speedup vs baseline: 1.0910x; 1.0112x over previous
#include <cuda_runtime.h>
#include <cuda_bf16.h>
#include <cuda_fp16.h>
#include <cstdint>
#include <cstddef>

#define N_ROWS 131072
#define DIM    512
#define NCLU   512

// ---------------------------------------------------------------------------
// Device-global scratch (centers only)
// ---------------------------------------------------------------------------
__device__ __half g_ch[(size_t)NCLU * DIM];
__device__ float g_c2[NCLU];

// ---------------------------------------------------------------------------
// Helpers (base ISA only)
// ---------------------------------------------------------------------------
__device__ __forceinline__ uint32_t smem_to_u32(const void* smem_ptr) {
    uint32_t addr;
    asm("{ .reg .u64 tmp; cvta.to.shared.u64 tmp, %1; cvt.u32.u64 %0, tmp; }"
        : "=r"(addr) : "l"(smem_ptr));
    return addr;
}
__device__ __forceinline__ void cp16(uint32_t dst_smem, const void* src) {
    asm volatile("cp.async.cg.shared.global [%0], [%1], 16;"
                 :: "r"(dst_smem), "l"(src));
}
__device__ __forceinline__ void cp_commit() {
    asm volatile("cp.async.commit_group;");
}
template <int N>
__device__ __forceinline__ void cp_wait() {
    asm volatile("cp.async.wait_group %0;" :: "n"(N));
}
__device__ __forceinline__ float frcp(float a) {
    float r;
    asm("rcp.approx.f32 %0, %1;" : "=f"(r) : "f"(a));
    return r;
}
__device__ __forceinline__ void ldsm4(uint32_t* r, uint32_t addr) {
    asm volatile("ldmatrix.sync.aligned.m8n8.x4.shared.b16 {%0,%1,%2,%3}, [%4];"
                 : "=r"(r[0]), "=r"(r[1]), "=r"(r[2]), "=r"(r[3]) : "r"(addr));
}
__device__ __forceinline__ float4 lds_f4(uint32_t addr) {
    float4 v;
    asm volatile("ld.shared.v4.f32 {%0,%1,%2,%3}, [%4];"
                 : "=f"(v.x), "=f"(v.y), "=f"(v.z), "=f"(v.w) : "r"(addr));
    return v;
}
__device__ __forceinline__ void sts_v2(uint32_t addr, uint32_t a, uint32_t b) {
    asm volatile("st.shared.v2.b32 [%0], {%1,%2};"
                 :: "r"(addr), "r"(a), "r"(b) : "memory");
}
// f16 x f16 -> f16 accumulate (hypothesis: 2x issue rate vs f32 accum)
__device__ __forceinline__ void mma16816h(uint32_t* c, const uint32_t* a, const uint32_t* b) {
    asm volatile(
        "mma.sync.aligned.m16n8k16.row.col.f16.f16.f16.f16 "
        "{%0,%1}, {%2,%3,%4,%5}, {%6,%7}, {%0,%1};"
        : "+r"(c[0]), "+r"(c[1])
        : "r"(a[0]), "r"(a[1]), "r"(a[2]), "r"(a[3]), "r"(b[0]), "r"(b[1]));
}
__device__ __forceinline__ uint32_t pack_f16(float a, float b) {
    union { __half2 h; uint32_t u; } pk;
    pk.h = __floats2half2_rn(a, b);
    return pk.u;
}

// ---------------------------------------------------------------------------
// Prep centers: fp32 -> fp16 + row norms (one row per warp). ~2us.
// ---------------------------------------------------------------------------
__global__ void prep_c_kernel(const float* __restrict__ c) {
    int row = blockIdx.x * 8 + (threadIdx.x >> 5);
    if (row >= NCLU) return;
    int lane = threadIdx.x & 31;
    const float4* sr = (const float4*)(c + (size_t)row * DIM);
    uint2* dr = (uint2*)(g_ch + (size_t)row * DIM);
    float s = 0.f;
    #pragma unroll
    for (int t = 0; t < 4; t++) {
        float4 v = sr[lane + 32 * t];
        s += v.x * v.x + v.y * v.y + v.z * v.z + v.w * v.w;
        uint2 u;
        u.x = pack_f16(v.x, v.y);
        u.y = pack_f16(v.z, v.w);
        dr[lane + 32 * t] = u;
    }
    #pragma unroll
    for (int o = 16; o; o >>= 1) s += __shfl_xor_sync(0xffffffffu, s, o);
    if (lane == 0) g_c2[row] = s;
}

// ---------------------------------------------------------------------------
// Fused GEMM + t-student epilogue. 256 threads, 8 warps (2m x 4n), warp tile
// 64x64, fp16 operands with fp16 accumulation. CTA tile 128x256; cluster of
// 2 covers 512 clusters. One __syncthreads per k-chunk; fp32->fp16 convert
// of A overlapped with MMA (each thread converts only its own bytes).
// ---------------------------------------------------------------------------
static constexpr int TM = 128, TN = 256, KC = 64, NUM_KC = DIM / KC;  // 8
static constexpr int AF_BYTES  = TM * KC * 4;            // 32768 / stage
static constexpr int ABF_BYTES = TM * KC * 2;            // 16384 / buf
static constexpr int B_BYTES   = TN * KC * 2;            // 32768 / stage
static constexpr int AF_OFF   = 0;                        // 2 stages
static constexpr int ABF_OFF  = 2 * AF_BYTES;             // 65536, 2 bufs
static constexpr int B_OFF    = ABF_OFF + 2 * ABF_BYTES;  // 98304, 2 stages
static constexpr int C2_OFF   = B_OFF + 2 * B_BYTES;      // 163840
static constexpr int X2P_OFF  = C2_OFF + NCLU * 4;        // 165888 (128x16)
static constexpr int X2_OFF   = X2P_OFF + TM * 16 * 4;    // 174080
static constexpr int RED_OFF  = X2_OFF + TM * 4;          // 174592 (128x4)
static constexpr int PEER_OFF = RED_OFF + TM * 4 * 4;     // 176640
static constexpr int INV_OFF  = PEER_OFF + TM * 4;        // 177152
static constexpr int SMEM_TOTAL = INV_OFF + TM * 4;       // 177664

__global__ void __launch_bounds__(256, 1) __cluster_dims__(2, 1, 1)
gemm_kernel(const float* __restrict__ x, float* __restrict__ out) {
    extern __shared__ __align__(1024) char smem[];
    uint32_t sb = smem_to_u32(smem);
    int tid = threadIdx.x;
    int wid = tid >> 5, lane = tid & 31;
    int mtile = blockIdx.x >> 1;
    int nhalf = blockIdx.x & 1;
    int warp_m = wid & 1;        // 2 x 64 rows
    int warp_n = wid >> 1;       // 4 x 64 cols

    float* c2s  = (float*)(smem + C2_OFF);
    float* x2p  = (float*)(smem + X2P_OFF);
    float* x2s  = (float*)(smem + X2_OFF);
    float* red  = (float*)(smem + RED_OFF);
    float* peer = (float*)(smem + PEER_OFF);
    float* invs = (float*)(smem + INV_OFF);

    for (int i = tid; i < NCLU; i += 256) c2s[i] = g_c2[i];

    const float* asrc0 = x + (size_t)mtile * TM * DIM;
    const __half* bsrc0 = g_ch + (size_t)nhalf * TN * DIM;

    // A chunk ownership: row = (tid>>4) + 16*i, cpos = tid&15
    int r0 = tid >> 4, cpos = tid & 15;

    auto load_A = [&](int kc, int s) {
        uint32_t Af = sb + AF_OFF + s * AF_BYTES;
        const float* asrc = asrc0 + kc * KC;
        #pragma unroll
        for (int i = 0; i < 8; i++) {
            int r = r0 + i * 16;
            cp16(Af + r * 256 + ((cpos * 16) ^ ((r & 7) << 4)),
                 asrc + (size_t)r * DIM + cpos * 4);
        }
        cp_commit();
    };
    auto load_B = [&](int kc, int s) {
        uint32_t Bb = sb + B_OFF + s * B_BYTES;
        const __half* bsrc = bsrc0 + kc * KC;
        #pragma unroll
        for (int i = 0; i < 8; i++) {
            int idx = tid + i * 256;
            int r = idx >> 3, c = idx & 7;
            cp16(Bb + r * 128 + ((c * 16) ^ ((r & 7) << 4)),
                 bsrc + (size_t)r * DIM + c * 8);
        }
        cp_commit();
    };

    float xpart[8] = {};

    auto convert = [&](int sf, int bf) {
        uint32_t Af = sb + AF_OFF + sf * AF_BYTES;
        uint32_t Ab = sb + ABF_OFF + bf * ABF_BYTES;
        #pragma unroll
        for (int i = 0; i < 8; i++) {
            int r = r0 + i * 16;
            uint32_t swz = (uint32_t)(r & 7) << 4;
            float4 v = lds_f4(Af + r * 256 + ((cpos * 16) ^ swz));
            xpart[i] += v.x * v.x + v.y * v.y + v.z * v.z + v.w * v.w;
            sts_v2(Ab + r * 128 + (((cpos >> 1) * 16) ^ swz) + (cpos & 1) * 8,
                   pack_f16(v.x, v.y), pack_f16(v.z, v.w));
        }
    };

    // ldmatrix lane addressing
    int ri = lane & 7;
    uint32_t mask = (uint32_t)ri << 4;
    uint32_t a_row0 = (uint32_t)(warp_m * 64 + ((lane >> 3) & 1) * 8 + ri) * 128;
    uint32_t akoff  = (uint32_t)(lane >> 4) * 16;
    uint32_t b_row0 = (uint32_t)(warp_n * 64 + (lane >> 4) * 8 + ri) * 128;
    uint32_t bkoff  = (uint32_t)((lane >> 3) & 1) * 16;

    uint32_t acc[4][8][2] = {};   // warp tile 64x64, f16x2 accumulators

    // ---- Prologue ----
    load_A(0, 0); load_B(0, 0);
    cp_wait<1>();
    convert(0, 0);
    load_A(1, 1); load_B(1, 1);
    cp_wait<2>();
    __syncthreads();

    for (int kc = 0; kc < NUM_KC; kc++) {
        int s = kc & 1;
        uint32_t Ab = sb + ABF_OFF + s * ABF_BYTES;
        uint32_t Bb = sb + B_OFF + s * B_BYTES;

        #pragma unroll
        for (int ks = 0; ks < 4; ks++) {
            if (ks == 2 && kc < NUM_KC - 1) {
                cp_wait<1>();
                convert(s ^ 1, s ^ 1);
            }
            uint32_t a[4][4], b[4][4];
            uint32_t akb = (akoff + ks * 32) ^ mask;
            uint32_t bkb = (bkoff + ks * 32) ^ mask;
            #pragma unroll
            for (int mt = 0; mt < 4; mt++)
                ldsm4(a[mt], Ab + a_row0 + (uint32_t)(mt * 2048) + akb);
            #pragma unroll
            for (int gg = 0; gg < 4; gg++)
                ldsm4(b[gg], Bb + b_row0 + (uint32_t)(gg * 2048) + bkb);
            #pragma unroll
            for (int mt = 0; mt < 4; mt++)
                #pragma unroll
                for (int nt = 0; nt < 8; nt++)
                    mma16816h(acc[mt][nt], a[mt], b[nt >> 1] + (nt & 1) * 2);
        }

        if (kc < NUM_KC - 1) cp_wait<0>();
        __syncthreads();
        if (kc + 2 < NUM_KC) { load_A(kc + 2, s); load_B(kc + 2, s); }
    }

    // ---------------- Epilogue ----------------
    #pragma unroll
    for (int i = 0; i < 8; i++) x2p[(r0 + i * 16) * 16 + cpos] = xpart[i];
    __syncthreads();
    if (tid < TM) {
        float s = 0.f;
        #pragma unroll
        for (int j = 0; j < 16; j++) s += x2p[tid * 16 + j];
        x2s[tid] = s;
    }
    __syncthreads();

    int g = lane >> 2, qa = lane & 3;
    float qv[4][8][4];           // fp32 q values (replaces acc reuse)
    float rs[4][2];
    #pragma unroll
    for (int mt = 0; mt < 4; mt++) {
        #pragma unroll
        for (int h = 0; h < 2; h++) {
            int row = warp_m * 64 + mt * 16 + h * 8 + g;
            float x2v = x2s[row];
            float p = 0.f;
            #pragma unroll
            for (int nt = 0; nt < 8; nt++) {
                int col = nhalf * 256 + warp_n * 64 + nt * 8 + qa * 2;
                union { uint32_t u; __half2 h2; } cvt;
                cvt.u = acc[mt][nt][h];
                float2 d = __half22float2(cvt.h2);
                float b0 = x2v + c2s[col];
                float b1 = x2v + c2s[col + 1];
                float q0 = frcp(1.f + fmaxf(fmaf(-2.f, d.x, b0), 0.f));
                float q1 = frcp(1.f + fmaxf(fmaf(-2.f, d.y, b1), 0.f));
                qv[mt][nt][h * 2 + 0] = q0;
                qv[mt][nt][h * 2 + 1] = q1;
                p += q0 + q1;
            }
            rs[mt][h] = p;
        }
    }
    #pragma unroll
    for (int mt = 0; mt < 4; mt++)
        #pragma unroll
        for (int h = 0; h < 2; h++) {
            rs[mt][h] += __shfl_xor_sync(0xffffffffu, rs[mt][h], 1);
            rs[mt][h] += __shfl_xor_sync(0xffffffffu, rs[mt][h], 2);
        }
    if (qa == 0) {
        #pragma unroll
        for (int mt = 0; mt < 4; mt++)
            #pragma unroll
            for (int h = 0; h < 2; h++)
                red[(warp_m * 64 + mt * 16 + h * 8 + g) * 4 + warp_n] = rs[mt][h];
    }
    __syncthreads();

    float L = 0.f;
    if (tid < TM) {
        L = red[tid * 4] + red[tid * 4 + 1] + red[tid * 4 + 2] + red[tid * 4 + 3];
        uint32_t paddr;
        asm volatile("mapa.shared::cluster.u32 %0, %1, %2;"
                     : "=r"(paddr) : "r"(sb + PEER_OFF + tid * 4), "r"(nhalf ^ 1));
        asm volatile("st.shared::cluster.f32 [%0], %1;" :: "r"(paddr), "f"(L) : "memory");
    }
    asm volatile("barrier.cluster.arrive.aligned;" ::: "memory");
    asm volatile("barrier.cluster.wait.aligned;" ::: "memory");
    if (tid < TM) invs[tid] = frcp(L + peer[tid]);
    __syncthreads();

    float* outbase = out + (size_t)mtile * TM * NCLU + nhalf * TN;
    #pragma unroll
    for (int mt = 0; mt < 4; mt++) {
        #pragma unroll
        for (int h = 0; h < 2; h++) {
            int row = warp_m * 64 + mt * 16 + h * 8 + g;
            float inv = invs[row];
            float* orow = outbase + (size_t)row * NCLU + warp_n * 64;
            #pragma unroll
            for (int nt = 0; nt < 8; nt++) {
                float2 v;
                v.x = qv[mt][nt][h * 2 + 0] * inv;
                v.y = qv[mt][nt][h * 2 + 1] * inv;
                *(float2*)(orow + nt * 8 + qa * 2) = v;
            }
        }
    }
}

// ---------------------------------------------------------------------------
// Launch
// ---------------------------------------------------------------------------
extern "C" void kernel_launch(void* const* d_in, const int* in_sizes, int n_in,
                              void* d_out, int out_size) {
    const float* x  = (const float*)d_in[0];
    const float* cc = (const float*)d_in[1];
    float* out = (float*)d_out;

    cudaFuncSetAttribute(gemm_kernel,
                         cudaFuncAttributeMaxDynamicSharedMemorySize, SMEM_TOTAL);

    prep_c_kernel<<<NCLU / 8, 256>>>(cc);
    gemm_kernel<<<(N_ROWS / TM) * 2, 256, SMEM_TOTAL>>>(x, out);
}

// round 9
// speedup vs baseline: 1.2943x; 1.1864x over previous
#include <cuda_runtime.h>
#include <cuda_bf16.h>
#include <cuda_fp16.h>
#include <cstdint>
#include <cstddef>

#define N_ROWS 131072
#define DIM    512
#define NCLU   512

// ---------------------------------------------------------------------------
// Device-global scratch (centers only)
// ---------------------------------------------------------------------------
__device__ __half g_ch[(size_t)NCLU * DIM];
__device__ float g_c2[NCLU];

// ---------------------------------------------------------------------------
// Helpers
// ---------------------------------------------------------------------------
__device__ __forceinline__ uint32_t smem_to_u32(const void* smem_ptr) {
    uint32_t addr;
    asm("{ .reg .u64 tmp; cvta.to.shared.u64 tmp, %1; cvt.u32.u64 %0, tmp; }"
        : "=r"(addr) : "l"(smem_ptr));
    return addr;
}
__device__ __forceinline__ void cp16(uint32_t dst_smem, const void* src) {
    asm volatile("cp.async.cg.shared.global [%0], [%1], 16;"
                 :: "r"(dst_smem), "l"(src));
}
__device__ __forceinline__ void cp_commit() {
    asm volatile("cp.async.commit_group;");
}
template <int N>
__device__ __forceinline__ void cp_wait() {
    asm volatile("cp.async.wait_group %0;" :: "n"(N));
}
__device__ __forceinline__ float frcp(float a) {
    float r;
    asm("rcp.approx.f32 %0, %1;" : "=f"(r) : "f"(a));
    return r;
}
__device__ __forceinline__ void ldsm4(uint32_t* r, uint32_t addr) {
    asm volatile("ldmatrix.sync.aligned.m8n8.x4.shared.b16 {%0,%1,%2,%3}, [%4];"
                 : "=r"(r[0]), "=r"(r[1]), "=r"(r[2]), "=r"(r[3]) : "r"(addr));
}
__device__ __forceinline__ float4 lds_f4(uint32_t addr) {
    float4 v;
    asm volatile("ld.shared.v4.f32 {%0,%1,%2,%3}, [%4];"
                 : "=f"(v.x), "=f"(v.y), "=f"(v.z), "=f"(v.w) : "r"(addr));
    return v;
}
__device__ __forceinline__ void sts_v2(uint32_t addr, uint32_t a, uint32_t b) {
    asm volatile("st.shared.v2.b32 [%0], {%1,%2};"
                 :: "r"(addr), "r"(a), "r"(b) : "memory");
}
__device__ __forceinline__ void mma16816h(uint32_t* c, const uint32_t* a, const uint32_t* b) {
    asm volatile(
        "mma.sync.aligned.m16n8k16.row.col.f16.f16.f16.f16 "
        "{%0,%1}, {%2,%3,%4,%5}, {%6,%7}, {%0,%1};"
        : "+r"(c[0]), "+r"(c[1])
        : "r"(a[0]), "r"(a[1]), "r"(a[2]), "r"(a[3]), "r"(b[0]), "r"(b[1]));
}
__device__ __forceinline__ uint32_t pack_f16(float a, float b) {
    union { __half2 h; uint32_t u; } pk;
    pk.h = __floats2half2_rn(a, b);
    return pk.u;
}

// ---------------------------------------------------------------------------
// Prep centers: fp32 -> fp16 + row norms (one row per warp). ~2us.
// ---------------------------------------------------------------------------
__global__ void prep_c_kernel(const float* __restrict__ c) {
    int row = blockIdx.x * 8 + (threadIdx.x >> 5);
    if (row >= NCLU) return;
    int lane = threadIdx.x & 31;
    const float4* sr = (const float4*)(c + (size_t)row * DIM);
    uint2* dr = (uint2*)(g_ch + (size_t)row * DIM);
    float s = 0.f;
    #pragma unroll
    for (int t = 0; t < 4; t++) {
        float4 v = sr[lane + 32 * t];
        s += v.x * v.x + v.y * v.y + v.z * v.z + v.w * v.w;
        uint2 u;
        u.x = pack_f16(v.x, v.y);
        u.y = pack_f16(v.z, v.w);
        dr[lane + 32 * t] = u;
    }
    #pragma unroll
    for (int o = 16; o; o >>= 1) s += __shfl_xor_sync(0xffffffffu, s, o);
    if (lane == 0) g_c2[row] = s;
}

// ---------------------------------------------------------------------------
// Fused GEMM + t-student epilogue. 512 threads, 16 warps (2m x 8n), warp tile
// 64x64, CTA tile 128x512 (full cluster row -> no cluster needed).
// fp16 operands, fp16 accumulate. Single fp32 A staging buffer (per-thread
// ownership), double-buffered fp16 A + B, one __syncthreads per k-chunk.
// ---------------------------------------------------------------------------
static constexpr int TM = 128, KC = 64, NUM_KC = DIM / KC;  // 8
static constexpr int AF_BYTES  = TM * KC * 4;              // 32768 (1 buf)
static constexpr int AHF_BYTES = TM * KC * 2;              // 16384 / buf
static constexpr int B_BYTES   = NCLU * KC * 2;            // 65536 / stage
static constexpr int AF_OFF   = 0;
static constexpr int AHF_OFF  = AF_BYTES;                   // 32768, 2 bufs
static constexpr int B_OFF    = AHF_OFF + 2 * AHF_BYTES;    // 65536, 2 stages
static constexpr int C2_OFF   = B_OFF + 2 * B_BYTES;        // 196608
static constexpr int X2P_OFF  = C2_OFF + NCLU * 4;          // 198656 (128x16)
static constexpr int X2_OFF   = X2P_OFF + TM * 16 * 4;      // 206848
static constexpr int RED_OFF  = X2_OFF + TM * 4;            // 207360 (128x8)
static constexpr int INV_OFF  = RED_OFF + TM * 8 * 4;       // 211456
static constexpr int SMEM_TOTAL = INV_OFF + TM * 4;         // 211968

__global__ void __launch_bounds__(512, 1)
gemm_kernel(const float* __restrict__ x, float* __restrict__ out) {
    extern __shared__ __align__(1024) char smem[];
    uint32_t sb = smem_to_u32(smem);
    int tid = threadIdx.x;
    int wid = tid >> 5, lane = tid & 31;
    int mtile = blockIdx.x;
    int warp_m = wid & 1;        // 2 x 64 rows
    int warp_n = wid >> 1;       // 8 x 64 cols

    float* c2s  = (float*)(smem + C2_OFF);
    float* x2p  = (float*)(smem + X2P_OFF);
    float* x2s  = (float*)(smem + X2_OFF);
    float* red  = (float*)(smem + RED_OFF);
    float* invs = (float*)(smem + INV_OFF);

    for (int i = tid; i < NCLU; i += 512) c2s[i] = g_c2[i];

    const float* asrc0 = x + (size_t)mtile * TM * DIM;

    // A chunk ownership (2048 chunks, 4/thread): r = (tid>>4)+32i, cpos = tid&15
    int r0 = tid >> 4, cpos = tid & 15;

    auto load_A = [&](int kc) {
        uint32_t Af = sb + AF_OFF;
        const float* asrc = asrc0 + kc * KC;
        #pragma unroll
        for (int i = 0; i < 4; i++) {
            int r = r0 + i * 32;
            cp16(Af + r * 256 + ((cpos * 16) ^ ((r & 7) << 4)),
                 asrc + (size_t)r * DIM + cpos * 4);
        }
        cp_commit();
    };
    auto load_B = [&](int kc, int s) {
        uint32_t Bb = sb + B_OFF + s * B_BYTES;
        const __half* bsrc = g_ch + kc * KC;
        #pragma unroll
        for (int i = 0; i < 8; i++) {       // 4096 chunks
            int idx = tid + i * 512;
            int r = idx >> 3, c = idx & 7;
            cp16(Bb + r * 128 + ((c * 16) ^ ((r & 7) << 4)),
                 bsrc + (size_t)r * DIM + c * 8);
        }
        cp_commit();
    };

    float xpart[4] = {};

    // Convert own chunks of AF -> Ahf[bf] (fp16, SW128), accumulate x^2.
    auto convert = [&](int bf) {
        uint32_t Af = sb + AF_OFF;
        uint32_t Ab = sb + AHF_OFF + bf * AHF_BYTES;
        #pragma unroll
        for (int i = 0; i < 4; i++) {
            int r = r0 + i * 32;
            uint32_t swz = (uint32_t)(r & 7) << 4;
            float4 v = lds_f4(Af + r * 256 + ((cpos * 16) ^ swz));
            xpart[i] += v.x * v.x + v.y * v.y + v.z * v.z + v.w * v.w;
            sts_v2(Ab + r * 128 + (((cpos >> 1) * 16) ^ swz) + (cpos & 1) * 8,
                   pack_f16(v.x, v.y), pack_f16(v.z, v.w));
        }
    };

    // ldmatrix lane addressing
    int ri = lane & 7;
    uint32_t mask = (uint32_t)ri << 4;
    uint32_t a_row0 = (uint32_t)(warp_m * 64 + ((lane >> 3) & 1) * 8 + ri) * 128;
    uint32_t akoff  = (uint32_t)(lane >> 4) * 16;
    uint32_t b_row0 = (uint32_t)(warp_n * 64 + (lane >> 4) * 8 + ri) * 128;
    uint32_t bkoff  = (uint32_t)((lane >> 3) & 1) * 16;

    uint32_t acc[4][8][2] = {};   // warp tile 64x64, f16x2 accumulators

    // ---- Prologue ----
    load_A(0); load_B(0, 0);      // groups: A0, B0
    cp_wait<1>();                 // A0 done (self chunks)
    convert(0);
    load_A(1); load_B(1, 1);      // outstanding: B0, A1, B1
    cp_wait<2>();                 // B0 done
    __syncthreads();              // Ahf0 + B0 visible

    for (int kc = 0; kc < NUM_KC; kc++) {
        int s = kc & 1;
        uint32_t Ab = sb + AHF_OFF + s * AHF_BYTES;
        uint32_t Bb = sb + B_OFF + s * B_BYTES;

        #pragma unroll
        for (int ks = 0; ks < 4; ks++) {
            if (ks == 2 && kc < NUM_KC - 1) {
                cp_wait<1>();                 // A[kc+1] done (self)
                convert(s ^ 1);               // overlap with remaining mma
            }
            uint32_t a[4][4], b[4][4];
            uint32_t akb = (akoff + ks * 32) ^ mask;
            uint32_t bkb = (bkoff + ks * 32) ^ mask;
            #pragma unroll
            for (int mt = 0; mt < 4; mt++)
                ldsm4(a[mt], Ab + a_row0 + (uint32_t)(mt * 2048) + akb);
            #pragma unroll
            for (int gg = 0; gg < 4; gg++)
                ldsm4(b[gg], Bb + b_row0 + (uint32_t)(gg * 2048) + bkb);
            #pragma unroll
            for (int mt = 0; mt < 4; mt++)
                #pragma unroll
                for (int nt = 0; nt < 8; nt++)
                    mma16816h(acc[mt][nt], a[mt], b[nt >> 1] + (nt & 1) * 2);
        }

        if (kc < NUM_KC - 1) cp_wait<0>();    // B[kc+1] done
        __syncthreads();                      // publish Ahf[s^1], B[kc+1]; AF reusable
        if (kc + 2 < NUM_KC) { load_A(kc + 2); load_B(kc + 2, s); }
    }

    // ---------------- Epilogue ----------------
    #pragma unroll
    for (int i = 0; i < 4; i++) x2p[(r0 + i * 32) * 16 + cpos] = xpart[i];
    __syncthreads();
    if (tid < TM) {
        float s = 0.f;
        #pragma unroll
        for (int j = 0; j < 16; j++) s += x2p[tid * 16 + j];
        x2s[tid] = s;
    }
    __syncthreads();

    int g = lane >> 2, qa = lane & 3;

    // Pass 1: row-sums of q (q recomputed later; saves 128 regs of scratch)
    float rs[4][2];
    #pragma unroll
    for (int mt = 0; mt < 4; mt++) {
        #pragma unroll
        for (int h = 0; h < 2; h++) {
            int row = warp_m * 64 + mt * 16 + h * 8 + g;
            float x2v = x2s[row];
            float p = 0.f;
            #pragma unroll
            for (int nt = 0; nt < 8; nt++) {
                int col = warp_n * 64 + nt * 8 + qa * 2;
                union { uint32_t u; __half2 h2; } cvt;
                cvt.u = acc[mt][nt][h];
                float2 d = __half22float2(cvt.h2);
                p += frcp(1.f + fmaxf(fmaf(-2.f, d.x, x2v + c2s[col]), 0.f));
                p += frcp(1.f + fmaxf(fmaf(-2.f, d.y, x2v + c2s[col + 1]), 0.f));
            }
            rs[mt][h] = p;
        }
    }
    #pragma unroll
    for (int mt = 0; mt < 4; mt++)
        #pragma unroll
        for (int h = 0; h < 2; h++) {
            rs[mt][h] += __shfl_xor_sync(0xffffffffu, rs[mt][h], 1);
            rs[mt][h] += __shfl_xor_sync(0xffffffffu, rs[mt][h], 2);
        }
    if (qa == 0) {
        #pragma unroll
        for (int mt = 0; mt < 4; mt++)
            #pragma unroll
            for (int h = 0; h < 2; h++)
                red[(warp_m * 64 + mt * 16 + h * 8 + g) * 8 + warp_n] = rs[mt][h];
    }
    __syncthreads();
    if (tid < TM) {
        float L = 0.f;
        #pragma unroll
        for (int j = 0; j < 8; j++) L += red[tid * 8 + j];
        invs[tid] = frcp(L);
    }
    __syncthreads();

    // Pass 2: recompute q, normalize, store
    float* outbase = out + (size_t)mtile * TM * NCLU;
    #pragma unroll
    for (int mt = 0; mt < 4; mt++) {
        #pragma unroll
        for (int h = 0; h < 2; h++) {
            int row = warp_m * 64 + mt * 16 + h * 8 + g;
            float x2v = x2s[row];
            float inv = invs[row];
            float* orow = outbase + (size_t)row * NCLU + warp_n * 64;
            #pragma unroll
            for (int nt = 0; nt < 8; nt++) {
                int col = warp_n * 64 + nt * 8 + qa * 2;
                union { uint32_t u; __half2 h2; } cvt;
                cvt.u = acc[mt][nt][h];
                float2 d = __half22float2(cvt.h2);
                float2 v;
                v.x = frcp(1.f + fmaxf(fmaf(-2.f, d.x, x2v + c2s[col]), 0.f)) * inv;
                v.y = frcp(1.f + fmaxf(fmaf(-2.f, d.y, x2v + c2s[col + 1]), 0.f)) * inv;
                *(float2*)(orow + nt * 8 + qa * 2) = v;
            }
        }
    }
}

// ---------------------------------------------------------------------------
// Launch
// ---------------------------------------------------------------------------
extern "C" void kernel_launch(void* const* d_in, const int* in_sizes, int n_in,
                              void* d_out, int out_size) {
    const float* x  = (const float*)d_in[0];
    const float* cc = (const float*)d_in[1];
    float* out = (float*)d_out;

    cudaFuncSetAttribute(gemm_kernel,
                         cudaFuncAttributeMaxDynamicSharedMemorySize, SMEM_TOTAL);

    prep_c_kernel<<<NCLU / 8, 256>>>(cc);
    gemm_kernel<<<N_ROWS / TM, 512, SMEM_TOTAL>>>(x, out);
}